// round 1
// baseline (speedup 1.0000x reference)
#include <cuda_runtime.h>
#include <cuda_bf16.h>

// Problem constants (from reference):
//   N_POINTS = 1048576, N_CLUSTERS = 16384, D_FEAT = 64
//   x[67] = [features[label][0..63], centers[label] - point]   (fp32)
//   h = relu(x @ W1[67,128] + b1)
//   out = relu(h @ W2[128,64] + b2)                            -> [N, 64] fp32
//
// Inputs (metadata order):
//   d_in[0] features  [16384*64] f32
//   d_in[1] labels    [1048576]  i32
//   d_in[2] centers   [16384*3]  f32
//   d_in[3] points    [1048576*3] f32
//   d_in[4] W1        [67*128]   f32
//   d_in[5] b1        [128]      f32
//   d_in[6] W2        [128*64]   f32
//   d_in[7] b2        [64]       f32

#define D_FEAT 64
#define D_IN_RAW 67
#define D_IN 68            // padded to multiple of 4 (pad weight = 0, pad x = 0)
#define H1 128
#define H2 64
#define TPB 256

// SMEM layout (floats):
//   sW1T [H1][D_IN]  : W1 transposed, row j = column j of W1 (contiguous dot rows)
//   sW2  [H1][H2]    : as-is (row j contiguous over k)
//   sB1  [H1], sB2 [H2]
#define SMEM_FLOATS (H1 * D_IN + H1 * H2 + H1 + H2)

__global__ __launch_bounds__(TPB, 1)
void fused_gather_mlp_kernel(const float* __restrict__ features,
                             const int*   __restrict__ labels,
                             const float* __restrict__ centers,
                             const float* __restrict__ points,
                             const float* __restrict__ W1,
                             const float* __restrict__ b1,
                             const float* __restrict__ W2,
                             const float* __restrict__ b2,
                             float*       __restrict__ out,
                             int n)
{
    extern __shared__ float smem[];
    float* sW1T = smem;                    // 128*68 = 8704
    float* sW2  = sW1T + H1 * D_IN;        // 8192
    float* sB1  = sW2  + H1 * H2;          // 128
    float* sB2  = sB1  + H1;               // 64

    // Stage weights into shared memory.
    for (int idx = threadIdx.x; idx < H1 * D_IN; idx += TPB) {
        int j = idx / D_IN;
        int i = idx - j * D_IN;
        sW1T[idx] = (i < D_IN_RAW) ? W1[i * H1 + j] : 0.0f;
    }
    for (int idx = threadIdx.x; idx < H1 * H2; idx += TPB)
        sW2[idx] = W2[idx];
    if (threadIdx.x < H1) sB1[threadIdx.x] = b1[threadIdx.x];
    if (threadIdx.x < H2) sB2[threadIdx.x] = b2[threadIdx.x];
    __syncthreads();

    int p = blockIdx.x * TPB + threadIdx.x;
    if (p >= n) return;

    int lab = labels[p];

    // Build x[68] in registers. Feature gather: 16 x LDG.128 (L2-resident table).
    float x[D_IN];
    const float4* f4 = reinterpret_cast<const float4*>(features + (size_t)lab * D_FEAT);
    #pragma unroll
    for (int i = 0; i < D_FEAT / 4; i++) {
        float4 v = f4[i];
        x[4 * i + 0] = v.x;
        x[4 * i + 1] = v.y;
        x[4 * i + 2] = v.z;
        x[4 * i + 3] = v.w;
    }
    x[64] = centers[lab * 3 + 0] - points[(size_t)p * 3 + 0];
    x[65] = centers[lab * 3 + 1] - points[(size_t)p * 3 + 1];
    x[66] = centers[lab * 3 + 2] - points[(size_t)p * 3 + 2];
    x[67] = 0.0f;  // pad

    // Output accumulators, init with b2 (bias added once).
    float acc[H2];
    #pragma unroll
    for (int k = 0; k < H2; k++) acc[k] = sB2[k];

    // Mainloop over the 128 hidden units. Hidden value h_j is computed and
    // immediately folded into acc[] (never materializing h[128]).
    // All weight LDS are warp-uniform -> broadcast, conflict-free.
    #pragma unroll 1
    for (int j = 0; j < H1; j++) {
        const float4* wrow = reinterpret_cast<const float4*>(sW1T + j * D_IN);
        float h0 = 0.f, h1 = 0.f, h2 = 0.f, h3 = 0.f;
        #pragma unroll
        for (int i = 0; i < D_IN / 4; i++) {
            float4 w = wrow[i];
            h0 = fmaf(x[4 * i + 0], w.x, h0);
            h1 = fmaf(x[4 * i + 1], w.y, h1);
            h2 = fmaf(x[4 * i + 2], w.z, h2);
            h3 = fmaf(x[4 * i + 3], w.w, h3);
        }
        float h = fmaxf((h0 + h1) + (h2 + h3) + sB1[j], 0.0f);

        const float4* w2row = reinterpret_cast<const float4*>(sW2 + j * H2);
        #pragma unroll
        for (int k = 0; k < H2 / 4; k++) {
            float4 w = w2row[k];
            acc[4 * k + 0] = fmaf(h, w.x, acc[4 * k + 0]);
            acc[4 * k + 1] = fmaf(h, w.y, acc[4 * k + 1]);
            acc[4 * k + 2] = fmaf(h, w.z, acc[4 * k + 2]);
            acc[4 * k + 3] = fmaf(h, w.w, acc[4 * k + 3]);
        }
    }

    // Final ReLU + store (256B contiguous per thread).
    float4* o4 = reinterpret_cast<float4*>(out + (size_t)p * H2);
    #pragma unroll
    for (int k = 0; k < H2 / 4; k++) {
        float4 v;
        v.x = fmaxf(acc[4 * k + 0], 0.0f);
        v.y = fmaxf(acc[4 * k + 1], 0.0f);
        v.z = fmaxf(acc[4 * k + 2], 0.0f);
        v.w = fmaxf(acc[4 * k + 3], 0.0f);
        o4[k] = v;
    }
}

extern "C" void kernel_launch(void* const* d_in, const int* in_sizes, int n_in,
                              void* d_out, int out_size)
{
    const float* features = (const float*)d_in[0];
    const int*   labels   = (const int*)  d_in[1];
    const float* centers  = (const float*)d_in[2];
    const float* points   = (const float*)d_in[3];
    const float* W1       = (const float*)d_in[4];
    const float* b1       = (const float*)d_in[5];
    const float* W2       = (const float*)d_in[6];
    const float* b2       = (const float*)d_in[7];
    float* out = (float*)d_out;

    int n = in_sizes[1];  // N_POINTS (labels element count)

    size_t smem_bytes = SMEM_FLOATS * sizeof(float);  // ~68.4 KB > 48KB default
    cudaFuncSetAttribute(fused_gather_mlp_kernel,
                         cudaFuncAttributeMaxDynamicSharedMemorySize,
                         (int)smem_bytes);

    int grid = (n + TPB - 1) / TPB;
    fused_gather_mlp_kernel<<<grid, TPB, smem_bytes>>>(
        features, labels, centers, points, W1, b1, W2, b2, out, n);
}

// round 4
// speedup vs baseline: 4.8637x; 4.8637x over previous
#include <cuda_runtime.h>
#include <cuda_fp16.h>
#include <cstdint>

// Fused gather + 2-layer MLP using legacy mma.sync (HMMA) fp16 path.
//   x[67+pad] = [features[lab] (64), centers[lab]-point (3)]
//   h = relu(x @ W1 + b1)   [128]
//   o = relu(h @ W2 + b2)   [64]
// fp16 inputs, fp32 accumulation. h is chained register-resident between the
// two GEMMs (D-fragment of layer1 == A-fragment of layer2).

#define TPB 256
#define TILES_PER_CTA 8
#define PTS_PER_CTA (TILES_PER_CTA * 128)

#define K1 80              // padded K for layer 1 (5 k-steps of 16)
#define XS 44              // X row stride in u32 (88 halfs) -> conflict-free
#define W1S 44             // W1T row stride in u32
#define W2S 68             // W2T row stride in u32 (136 halfs) -> conflict-free

// smem layout in u32 words
#define S_X   0                         // [128][44]
#define S_W1  (S_X + 128 * XS)          // [128][44]
#define S_W2  (S_W1 + 128 * W1S)        // [64][68]
#define S_B1  (S_W2 + 64 * W2S)         // 128 floats
#define S_B2  (S_B1 + 128)              // 64 floats
#define S_TOT (S_B2 + 64)
#define SMEM_BYTES (S_TOT * 4)          // 63232 B -> needs MaxDynamicSharedMemorySize opt-in

__device__ __forceinline__ void mma16816(float* d, const uint32_t* a,
                                         uint32_t b0, uint32_t b1) {
    asm volatile(
        "mma.sync.aligned.m16n8k16.row.col.f32.f16.f16.f32 "
        "{%0,%1,%2,%3}, {%4,%5,%6,%7}, {%8,%9}, {%0,%1,%2,%3};"
        : "+f"(d[0]), "+f"(d[1]), "+f"(d[2]), "+f"(d[3])
        : "r"(a[0]), "r"(a[1]), "r"(a[2]), "r"(a[3]), "r"(b0), "r"(b1));
}

__device__ __forceinline__ uint32_t pack2(float x, float y) {
    __half2 h = __floats2half2_rn(x, y);
    return *reinterpret_cast<uint32_t*>(&h);
}
__device__ __forceinline__ uint32_t rpack2(float x, float y) {
    return pack2(fmaxf(x, 0.0f), fmaxf(y, 0.0f));
}

__global__ __launch_bounds__(TPB, 2)
void fused_mlp_hmma_kernel(const float* __restrict__ features,
                           const int*   __restrict__ labels,
                           const float* __restrict__ centers,
                           const float* __restrict__ points,
                           const float* __restrict__ W1,
                           const float* __restrict__ b1,
                           const float* __restrict__ W2,
                           const float* __restrict__ b2,
                           float*       __restrict__ out,
                           int n)
{
    extern __shared__ uint32_t sm[];

    const int tid  = threadIdx.x;
    const int lane = tid & 31;
    const int warp = tid >> 5;
    const int gid  = lane >> 2;   // group id (0..7)
    const int tig  = lane & 3;    // thread in group (0..3)

    // ---------------- one-time per CTA: stage weights (fp16, transposed) ----
    // W1T[n][k] = W1[k][n], k < 67, zero-padded to K1=80 (slots 0..39 read).
    for (int idx = tid; idx < 128 * XS; idx += TPB) {
        int nn = idx / XS;            // hidden unit
        int ku = idx - nn * XS;       // u32 slot = k pair
        int k0 = 2 * ku;
        float v0 = (k0     < 67) ? W1[k0 * 128 + nn] : 0.0f;
        float v1 = (k0 + 1 < 67) ? W1[(k0 + 1) * 128 + nn] : 0.0f;
        sm[S_W1 + idx] = pack2(v0, v1);
    }
    // W2T[n][k] = W2[k][n], k < 128
    for (int idx = tid; idx < 64 * W2S; idx += TPB) {
        int nn = idx / W2S;
        int ku = idx - nn * W2S;
        int k0 = 2 * ku;
        float v0 = (k0     < 128) ? W2[k0 * 64 + nn] : 0.0f;
        float v1 = (k0 + 1 < 128) ? W2[(k0 + 1) * 64 + nn] : 0.0f;
        sm[S_W2 + idx] = pack2(v0, v1);
    }
    if (tid < 128) ((float*)&sm[S_B1])[tid] = b1[tid];
    if (tid < 64)  ((float*)&sm[S_B2])[tid] = b2[tid];

    const int cta_base = blockIdx.x * PTS_PER_CTA;
    const int m0 = warp * 16;

    for (int t = 0; t < TILES_PER_CTA; t++) {
        const int tile_base = cta_base + t * 128;

        // ---------------- gather + fp32->fp16 into X smem (2 thr / row) -----
        {
            const int r    = tid >> 1;
            const int half = tid & 1;
            const int p    = tile_base + r;
            const int lab  = labels[p];
            const float4* f4 = (const float4*)(features) + (size_t)lab * 16;
            uint32_t* xrow = &sm[S_X + r * XS];
            if (half == 0) {
                #pragma unroll
                for (int i = 0; i < 8; i++) {
                    float4 v = __ldg(f4 + i);
                    xrow[2 * i]     = pack2(v.x, v.y);
                    xrow[2 * i + 1] = pack2(v.z, v.w);
                }
            } else {
                #pragma unroll
                for (int i = 8; i < 16; i++) {
                    float4 v = __ldg(f4 + i);
                    xrow[2 * i]     = pack2(v.x, v.y);
                    xrow[2 * i + 1] = pack2(v.z, v.w);
                }
                float cx = centers[lab * 3 + 0] - points[(size_t)p * 3 + 0];
                float cy = centers[lab * 3 + 1] - points[(size_t)p * 3 + 1];
                float cz = centers[lab * 3 + 2] - points[(size_t)p * 3 + 2];
                xrow[32] = pack2(cx, cy);
                xrow[33] = pack2(cz, 0.0f);
                #pragma unroll
                for (int u = 34; u < 40; u++) xrow[u] = 0u;  // k = 68..79
            }
        }
        __syncthreads();

        // ---------------- layer 1: A fragments (X) -------------------------
        uint32_t a[20];
        {
            const uint32_t r0 = (uint32_t)(m0 + gid) * XS;
            const uint32_t r1 = r0 + 8 * XS;
            #pragma unroll
            for (int s = 0; s < 5; s++) {
                const uint32_t c0 = 8 * s + tig;
                a[4 * s + 0] = sm[S_X + r0 + c0];
                a[4 * s + 1] = sm[S_X + r1 + c0];
                a[4 * s + 2] = sm[S_X + r0 + c0 + 4];
                a[4 * s + 3] = sm[S_X + r1 + c0 + 4];
            }
        }

        float acc1[64];
        #pragma unroll
        for (int i = 0; i < 64; i++) acc1[i] = 0.0f;

        #pragma unroll
        for (int j = 0; j < 16; j++) {          // 16 n-tiles of 8 hidden units
            const uint32_t bn = S_W1 + (uint32_t)(8 * j + gid) * W1S + tig;
            #pragma unroll
            for (int s = 0; s < 5; s++) {       // K = 80
                uint32_t b0 = sm[bn + 8 * s];
                uint32_t b1r = sm[bn + 8 * s + 4];
                mma16816(&acc1[4 * j], &a[4 * s], b0, b1r);
            }
        }

        // -------- epilogue 1: relu(acc+b1) -> layer-2 A fragments (regs) ----
        uint32_t ha[32];
        {
            const float* sB1f = (const float*)&sm[S_B1];
            #pragma unroll
            for (int j2 = 0; j2 < 8; j2++) {
                const int nlo = 16 * j2 + 2 * tig;
                float2 bl = *(const float2*)&sB1f[nlo];
                float2 bh = *(const float2*)&sB1f[nlo + 8];
                const float* cl = &acc1[8 * j2];       // n-tile 2*j2
                const float* ch = &acc1[8 * j2 + 4];   // n-tile 2*j2+1
                ha[4 * j2 + 0] = rpack2(cl[0] + bl.x, cl[1] + bl.y);
                ha[4 * j2 + 1] = rpack2(cl[2] + bl.x, cl[3] + bl.y);
                ha[4 * j2 + 2] = rpack2(ch[0] + bh.x, ch[1] + bh.y);
                ha[4 * j2 + 3] = rpack2(ch[2] + bh.x, ch[3] + bh.y);
            }
        }

        // ---------------- layer 2: h (regs) x W2T --------------------------
        float acc2[32];
        #pragma unroll
        for (int i = 0; i < 32; i++) acc2[i] = 0.0f;

        #pragma unroll
        for (int j = 0; j < 8; j++) {           // 8 n-tiles of 8 outputs
            const uint32_t bn = S_W2 + (uint32_t)(8 * j + gid) * W2S + tig;
            #pragma unroll
            for (int s = 0; s < 8; s++) {       // K = 128
                uint32_t b0 = sm[bn + 8 * s];
                uint32_t b1r = sm[bn + 8 * s + 4];
                mma16816(&acc2[4 * j], &ha[4 * s], b0, b1r);
            }
        }

        // ---------------- epilogue 2: relu + bias, direct stores ------------
        {
            const float* sB2f = (const float*)&sm[S_B2];
            float* o0 = out + (size_t)(tile_base + m0 + gid) * 64;
            float* o1 = o0 + 8 * 64;
            #pragma unroll
            for (int j = 0; j < 8; j++) {
                const int nn = 8 * j + 2 * tig;
                float2 bv = *(const float2*)&sB2f[nn];
                float2 v0, v1;
                v0.x = fmaxf(acc2[4 * j + 0] + bv.x, 0.0f);
                v0.y = fmaxf(acc2[4 * j + 1] + bv.y, 0.0f);
                v1.x = fmaxf(acc2[4 * j + 2] + bv.x, 0.0f);
                v1.y = fmaxf(acc2[4 * j + 3] + bv.y, 0.0f);
                *(float2*)(o0 + nn) = v0;
                *(float2*)(o1 + nn) = v1;
            }
        }
        __syncthreads();   // X reused by next tile's gather
    }
}

extern "C" void kernel_launch(void* const* d_in, const int* in_sizes, int n_in,
                              void* d_out, int out_size)
{
    const float* features = (const float*)d_in[0];
    const int*   labels   = (const int*)  d_in[1];
    const float* centers  = (const float*)d_in[2];
    const float* points   = (const float*)d_in[3];
    const float* W1       = (const float*)d_in[4];
    const float* b1       = (const float*)d_in[5];
    const float* W2       = (const float*)d_in[6];
    const float* b2       = (const float*)d_in[7];
    float* out = (float*)d_out;

    int n = in_sizes[1];                  // N_POINTS = 1048576
    int grid = n / PTS_PER_CTA;           // 1024

    // 63232 B dynamic smem > 48 KB default: must opt in (this was the R3 bug).
    cudaFuncSetAttribute(fused_mlp_hmma_kernel,
                         cudaFuncAttributeMaxDynamicSharedMemorySize,
                         (int)SMEM_BYTES);

    fused_mlp_hmma_kernel<<<grid, TPB, SMEM_BYTES>>>(
        features, labels, centers, points, W1, b1, W2, b2, out, n);
}